// round 17
// baseline (speedup 1.0000x reference)
#include <cuda_runtime.h>
#include <cstdint>

// gRNN over 1024 complete binary trees, depth 10, hidden SIZE=100.
// Between levels we store DUPLICATED comb pair-sums, k-major:
//   comb[o][m] = float2{s, s}  (so the f32x2 A-operand is a direct LDS).
// GEMM levels (L8..L5): TM=64, 320 thr, split-K, 3 CTAs/SM, cp.async staging.
// Inner loop: 1 LDS.128 (A pair) + 2 LDS.128 + 1 LDS.64 (B) + 10 fma2.
// L4..L0 + projection: tail kernel, 4 trees/CTA, grid 256 (single wave).

#define S      100
#define OPD    104     // Ww_s row stride (floats), mult of 4 for LDS.128
#define TM     64      // node rows per CTA
#define KH     50      // k-half size (split-K staging)
#define NTH    320
#define NTREES 1024
#define NNODES 1023
#define TPC    4       // trees per CTA in tail
#define HS     68      // tail h buffer stride (floats)

typedef unsigned long long u64;

// Duplicated comb buffers, k-major: buf[o * M + m] = {s,s}.
__device__ __align__(16) float2 g_bufA[NTREES * 64 * S];    // comb6, comb4
__device__ __align__(16) float2 g_bufB[NTREES * 128 * S];   // comb7, comb5

__device__ __forceinline__ u64 pack2(float x, float y) {
    u64 r; asm("mov.b64 %0, {%1,%2};" : "=l"(r) : "f"(x), "f"(y)); return r;
}
__device__ __forceinline__ void unpack2(u64 v, float& x, float& y) {
    asm("mov.b64 {%0,%1}, %2;" : "=f"(x), "=f"(y) : "l"(v));
}
__device__ __forceinline__ u64 fma2(u64 a, u64 b, u64 c) {
    u64 d; asm("fma.rn.f32x2 %0, %1, %2, %3;" : "=l"(d) : "l"(a), "l"(b), "l"(c));
    return d;
}
__device__ __forceinline__ void cpa16(uint32_t dst, const float* src) {
    asm volatile("cp.async.cg.shared.global [%0], [%1], 16;" :: "r"(dst), "l"(src));
}
__device__ __forceinline__ void cpa_commit() { asm volatile("cp.async.commit_group;" ::: "memory"); }
__device__ __forceinline__ void cpa_wait0()  { asm volatile("cp.async.wait_group 0;" ::: "memory"); }

#define LEVEL_SMEM (KH*TM*8 + (S*OPD + 3*S + 128) * (int)sizeof(float))
#define TAIL_SMEM  ((S*102 + 2*S*HS + 3*S) * (int)sizeof(float))

// ---------------------------------------------------------------------------
// Level kernel (TM=64). combprev: duplicated comb, [k][M] float2.
// Writes combnext[o][m] = {h[2m]+h[2m+1], same}.
// lane -> rows (2*lane, 2*lane+1); warp -> cols {8w..8w+7, 80+2w, 80+2w+1}.
// ---------------------------------------------------------------------------
template<bool LEAF>
__global__ __launch_bounds__(NTH, 3)
void level64(const float* __restrict__ times,
             const float* __restrict__ Qw,
             const float* __restrict__ Qb,
             const float* __restrict__ Ww,
             const float* __restrict__ Wb,
             const float2* __restrict__ combprev,
             float2* __restrict__ combnext,
             int d)
{
    extern __shared__ __align__(16) char smraw[];
    u64*   comb_s = (u64*)smraw;                      // [KH][TM] duplicated
    float* Ww_s   = (float*)(smraw + KH * TM * 8);    // [S][OPD] k-major
    float* Qw_s   = Ww_s + S * OPD;
    float* Qb_s   = Qw_s + S;
    float* Wb_s   = Qb_s + S;
    float* t_s    = Wb_s + S;                         // [128] leaf only

    const int tid     = threadIdx.x;
    const int lane    = tid & 31;
    const int warp    = tid >> 5;
    const int lvl     = 1 << d;
    const int M       = NTREES << d;
    const int baseRow = blockIdx.x * TM;

    // ---- async stage of one duplicated comb k-half ----
    auto stage_async = [&](int k0) {
        uint32_t cbase = (uint32_t)__cvta_generic_to_shared(comb_s);
#pragma unroll
        for (int i = 0; i < 5; i++) {
            int idx = tid + i * NTH;             // 0..1599 chunks of 16B
            int k = idx >> 5;                    // 0..49
            int j = (idx & 31) * 2;              // entry offset 0..62
            cpa16(cbase + (uint32_t)(k * TM + j) * 8u,
                  (const float*)(combprev + (long)(k0 + k) * M + baseRow + j));
        }
        cpa_commit();
    };

    if (!LEAF) stage_async(0);

    // stage weights (overlaps cp.async latency)
    for (int idx = tid; idx < S; idx += NTH) {
        Qw_s[idx] = Qw[idx];
        Qb_s[idx] = Qb[idx];
        Wb_s[idx] = Wb[idx];
    }
    for (int idx = tid; idx < S * S; idx += NTH) {
        int o = idx / S, k = idx % S;
        Ww_s[k * OPD + o] = Ww[idx];
    }
    if (LEAF) {
        // children times of rows baseRow..baseRow+63: 128 contiguous floats
        int b  = baseRow >> 8;
        int n0 = baseRow & 255;
        const float* tc = times + (long)b * NNODES + (2 * lvl - 1) + 2 * n0;
        if (tid < 128) t_s[tid] = tc[tid];
    }

    u64 acc[2][5];
#pragma unroll
    for (int r = 0; r < 2; r++)
#pragma unroll
        for (int c = 0; c < 5; c++) acc[r][c] = 0ull;

#pragma unroll 1
    for (int half = 0; half < 2; half++) {
        const int k0 = half * KH;

        if (LEAF) {
            __syncthreads();     // weights ready (h0) / prev GEMM done (h1)
            for (int idx = tid; idx < KH * TM; idx += NTH) {
                int kk = idx >> 6, r = idx & 63;
                int k = k0 + kk;
                float qw = Qw_s[k], qb = Qb_s[k];
                float v = fmaxf(fmaf(t_s[2 * r],     qw, qb), 0.f)
                        + fmaxf(fmaf(t_s[2 * r + 1], qw, qb), 0.f);
                comb_s[kk * TM + r] = pack2(v, v);
            }
            __syncthreads();
        } else {
            if (half == 1) { __syncthreads(); stage_async(KH); }
            cpa_wait0();
            __syncthreads();
        }

        // ---- packed-f32x2 GEMM over this k-half ----
#pragma unroll 2
        for (int kk = 0; kk < KH; kk++) {
            const ulonglong2 Av = *(const ulonglong2*)&comb_s[kk * TM + 2 * lane];
            const float* wr = Ww_s + (k0 + kk) * OPD;
            const ulonglong2 B01 = *(const ulonglong2*)(wr + 8 * warp);      // cols 8w..8w+3
            const ulonglong2 B23 = *(const ulonglong2*)(wr + 8 * warp + 4);  // cols 8w+4..8w+7
            const u64 B4 = *(const u64*)(wr + 80 + 2 * warp);                // cols 80+2w,+1
            acc[0][0] = fma2(Av.x, B01.x, acc[0][0]);
            acc[1][0] = fma2(Av.y, B01.x, acc[1][0]);
            acc[0][1] = fma2(Av.x, B01.y, acc[0][1]);
            acc[1][1] = fma2(Av.y, B01.y, acc[1][1]);
            acc[0][2] = fma2(Av.x, B23.x, acc[0][2]);
            acc[1][2] = fma2(Av.y, B23.x, acc[1][2]);
            acc[0][3] = fma2(Av.x, B23.y, acc[0][3]);
            acc[1][3] = fma2(Av.y, B23.y, acc[1][3]);
            acc[0][4] = fma2(Av.x, B4,    acc[0][4]);
            acc[1][4] = fma2(Av.y, B4,    acc[1][4]);
        }
    }

    // ---- epilogue: h = relu(acc + Wb + t*Qw + Qb); store duplicated pair-sum
    float tv[2];
#pragma unroll
    for (int r = 0; r < 2; r++) {
        int g = baseRow + 2 * lane + r;
        int b = g >> d;
        int n = g & (lvl - 1);
        tv[r] = times[(long)b * NNODES + (lvl - 1) + n];
    }
    const int Mn = M >> 1;
    const int m  = (baseRow >> 1) + lane;
#pragma unroll
    for (int c = 0; c < 5; c++) {
        const int o0 = (c < 4) ? (8 * warp + 2 * c) : (80 + 2 * warp);
        float x0, y0, x1, y1;
        unpack2(acc[0][c], x0, y0);     // row 2*lane:   cols o0, o0+1
        unpack2(acc[1][c], x1, y1);     // row 2*lane+1: cols o0, o0+1
        float h00 = fmaxf(x0 + Wb_s[o0]     + fmaf(tv[0], Qw_s[o0],     Qb_s[o0]),     0.f);
        float h01 = fmaxf(x1 + Wb_s[o0]     + fmaf(tv[1], Qw_s[o0],     Qb_s[o0]),     0.f);
        float h10 = fmaxf(y0 + Wb_s[o0 + 1] + fmaf(tv[0], Qw_s[o0 + 1], Qb_s[o0 + 1]), 0.f);
        float h11 = fmaxf(y1 + Wb_s[o0 + 1] + fmaf(tv[1], Qw_s[o0 + 1], Qb_s[o0 + 1]), 0.f);
        float s0 = h00 + h01;
        float s1 = h10 + h11;
        combnext[(long)o0 * Mn + m]       = make_float2(s0, s0);
        combnext[(long)(o0 + 1) * Mn + m] = make_float2(s1, s1);
    }
}

// ---------------------------------------------------------------------------
// Tail kernel: TPC=4 trees per CTA, levels 4..0 + projection. grid = 256.
// prev = duplicated comb4, [k][16384] float2; staged to plain f32 in smem.
// ---------------------------------------------------------------------------
__global__ __launch_bounds__(NTH, 2)
void tail_kernel(const float* __restrict__ times,
                 const float* __restrict__ Qw,
                 const float* __restrict__ Qb,
                 const float* __restrict__ Ww,
                 const float* __restrict__ Wb,
                 const float* __restrict__ Pw,
                 const float* __restrict__ Pb,
                 const float2* __restrict__ prev,
                 float* __restrict__ out)
{
    extern __shared__ float sm[];
    float* Ww_s = sm;                  // [S][102]
    float* bufA = Ww_s + S * 102;      // [S][HS]
    float* bufB = bufA + S * HS;       // [S][HS]
    float* Qw_s = bufB + S * HS;
    float* Qb_s = Qw_s + S;
    float* Wb_s = Qb_s + S;

    const int tid   = threadIdx.x;
    const int tree0 = blockIdx.x * TPC;
    const int M4    = NTREES * 16;

    for (int idx = tid; idx < S; idx += NTH) {
        Qw_s[idx] = Qw[idx];
        Qb_s[idx] = Qb[idx];
        Wb_s[idx] = Wb[idx];
    }
    for (int idx = tid; idx < S * S; idx += NTH) {
        int o = idx / S, k = idx % S;
        Ww_s[k * 102 + o] = Ww[idx];
    }
    // stage comb4 (convert duplicated -> plain)
    for (int idx = tid; idx < 64 * S; idx += NTH) {
        int k = idx >> 6, r = idx & 63;
        bufA[k * HS + r] = prev[(long)k * M4 + tree0 * 16 + r].x;
    }
    __syncthreads();

    const int lane = tid & 31;
    const int warp = tid >> 5;
    const int c0   = warp * 10;
    const int r0   = 2 * lane;

    float* hin  = bufA;
    float* hout = bufB;

#pragma unroll 1
    for (int d = 4; d >= 0; d--) {
        const int Mout = TPC << d;     // 64, 32, 16, 8, 4
        if (r0 < Mout) {
            u64 acc[2][5];
#pragma unroll
            for (int r = 0; r < 2; r++)
#pragma unroll
                for (int c = 0; c < 5; c++) acc[r][c] = 0ull;

            if (d == 4) {
                // comb prebuilt: one float per row
#pragma unroll 2
                for (int k = 0; k < S; k++) {
                    const float2 a2 = *(const float2*)&hin[k * HS + r0];
                    u64 A0 = pack2(a2.x, a2.x);
                    u64 A1 = pack2(a2.y, a2.y);
                    const u64* wrow = (const u64*)&Ww_s[k * 102 + c0];
#pragma unroll
                    for (int c = 0; c < 5; c++) {
                        u64 B = wrow[c];
                        acc[0][c] = fma2(A0, B, acc[0][c]);
                        acc[1][c] = fma2(A1, B, acc[1][c]);
                    }
                }
            } else {
                // read child h pairs: rows 2*r0 .. 2*r0+3 = one float4
#pragma unroll 2
                for (int k = 0; k < S; k++) {
                    const float4 h4 = *(const float4*)&hin[k * HS + 2 * r0];
                    float a0 = h4.x + h4.y;
                    float a1 = h4.z + h4.w;
                    u64 A0 = pack2(a0, a0);
                    u64 A1 = pack2(a1, a1);
                    const u64* wrow = (const u64*)&Ww_s[k * 102 + c0];
#pragma unroll
                    for (int c = 0; c < 5; c++) {
                        u64 B = wrow[c];
                        acc[0][c] = fma2(A0, B, acc[0][c]);
                        acc[1][c] = fma2(A1, B, acc[1][c]);
                    }
                }
            }

            float tv[2];
#pragma unroll
            for (int r = 0; r < 2; r++) {
                int rr = r0 + r;
                int t = rr >> d, n = rr & ((1 << d) - 1);
                tv[r] = times[(long)(tree0 + t) * NNODES + (1 << d) - 1 + n];
            }
#pragma unroll
            for (int c = 0; c < 5; c++) {
                int o0 = c0 + 2 * c;
                float x0, y0, x1, y1;
                unpack2(acc[0][c], x0, y0);
                unpack2(acc[1][c], x1, y1);
                float h00 = fmaxf(x0 + Wb_s[o0]   + fmaf(tv[0], Qw_s[o0],   Qb_s[o0]),   0.f);
                float h01 = fmaxf(x1 + Wb_s[o0]   + fmaf(tv[1], Qw_s[o0],   Qb_s[o0]),   0.f);
                float h10 = fmaxf(y0 + Wb_s[o0+1] + fmaf(tv[0], Qw_s[o0+1], Qb_s[o0+1]), 0.f);
                float h11 = fmaxf(y1 + Wb_s[o0+1] + fmaf(tv[1], Qw_s[o0+1], Qb_s[o0+1]), 0.f);
                *(float2*)&hout[o0 * HS + r0]       = make_float2(h00, h01);
                *(float2*)&hout[(o0 + 1) * HS + r0] = make_float2(h10, h11);
            }
        }
        __syncthreads();
        float* tp = hin; hin = hout; hout = tp;
    }

    // Roots: hin[o*HS + t], t = 0..3. 20 outputs, 2 per warp.
#pragma unroll
    for (int j = 0; j < 2; j++) {
        int oidx = 2 * warp + j;       // 0..19
        int t = oidx / 5, p = oidx % 5;
        float s = 0.f;
        for (int o = lane; o < S; o += 32)
            s = fmaf(hin[o * HS + t], Pw[p * S + o], s);
#pragma unroll
        for (int off = 16; off; off >>= 1)
            s += __shfl_down_sync(0xffffffffu, s, off);
        if (lane == 0)
            out[(long)(tree0 + t) * 5 + p] = s + Pb[p];
    }
}

// ---------------------------------------------------------------------------
extern "C" void kernel_launch(void* const* d_in, const int* in_sizes, int n_in,
                              void* d_out, int out_size)
{
    const float* times = (const float*)d_in[0];
    const float* Qw    = (const float*)d_in[1];
    const float* Qb    = (const float*)d_in[2];
    const float* Ww    = (const float*)d_in[3];
    const float* Wb    = (const float*)d_in[4];
    const float* Pw    = (const float*)d_in[5];
    const float* Pb    = (const float*)d_in[6];
    float* out = (float*)d_out;

    float2 *pA = nullptr, *pB = nullptr;
    cudaGetSymbolAddress((void**)&pA, g_bufA);
    cudaGetSymbolAddress((void**)&pB, g_bufB);

    cudaFuncSetAttribute(level64<true>,
                         cudaFuncAttributeMaxDynamicSharedMemorySize, LEVEL_SMEM);
    cudaFuncSetAttribute(level64<false>,
                         cudaFuncAttributeMaxDynamicSharedMemorySize, LEVEL_SMEM);
    cudaFuncSetAttribute(tail_kernel,
                         cudaFuncAttributeMaxDynamicSharedMemorySize, TAIL_SMEM);

    // L8 (leaf comb from times) -> comb7 in bufB   (M=262144, grid 4096)
    level64<true><<<(NTREES * 256) / TM, NTH, LEVEL_SMEM>>>(
        times, Qw, Qb, Ww, Wb, nullptr, pB, 8);
    // L7: comb7 -> comb6 in bufA                   (M=131072, grid 2048)
    level64<false><<<(NTREES * 128) / TM, NTH, LEVEL_SMEM>>>(
        times, Qw, Qb, Ww, Wb, pB, pA, 7);
    // L6: comb6 -> comb5 in bufB                   (M=65536, grid 1024)
    level64<false><<<(NTREES * 64) / TM, NTH, LEVEL_SMEM>>>(
        times, Qw, Qb, Ww, Wb, pA, pB, 6);
    // L5: comb5 -> comb4 in bufA                   (M=32768, grid 512)
    level64<false><<<(NTREES * 32) / TM, NTH, LEVEL_SMEM>>>(
        times, Qw, Qb, Ww, Wb, pB, pA, 5);

    // L4..L0 + projection: 4 trees/CTA, grid 256
    tail_kernel<<<NTREES / TPC, NTH, TAIL_SMEM>>>(
        times, Qw, Qb, Ww, Wb, Pw, Pb, pA, out);
}